// round 3
// baseline (speedup 1.0000x reference)
#include <cuda_runtime.h>
#include <math.h>

#define NN 3000
#define EE 48000
#define FF 32
#define GRID 148
#define TPB 672
#define NWARP 21
#define EXCL 1200
#define KSELF 10800.0f
#define ROWCAP 64
#define NRMAX 21
#define BMW (NRMAX * 94)          // dedup bitmap words (21 rows x 3000 bits)

// ---------------- global state (static, no allocation) ----------------
__device__ float g_A[NN * FF];
__device__ float g_B[NN * FF];
__device__ float g_C[NN * FF];
__device__ float g_Y1[NN * FF];
__device__ float g_X1[NN * FF];
__device__ unsigned long long g_keys[NN];
__device__ float g_part[GRID * FF];
__device__ unsigned int g_flags[GRID * 8];   // 32B-strided flags, monotonic across launches

// ---------------- grid barrier: per-block flag + parallel poll ----------------
__device__ __forceinline__ void gsync(unsigned int target) {
    __syncthreads();
    if (threadIdx.x == 0) {
        __threadfence();   // publish this block's global writes before flag
        *(volatile unsigned int*)&g_flags[blockIdx.x * 8] = target;
    }
    if (threadIdx.x < 32) {
        bool done = false;
        while (!done) {
            done = true;
#pragma unroll
            for (int k = 0; k < 5; ++k) {
                int b = (int)threadIdx.x + k * 32;
                if (b < GRID)
                    done &= (*(volatile unsigned int*)&g_flags[b * 8] >= target);
            }
        }
        __threadfence();
    }
    __syncthreads();
}

__device__ __forceinline__ unsigned int f2ord(float f) {
    unsigned int u = __float_as_uint(f);
    return (u & 0x80000000u) ? ~u : (u | 0x80000000u);
}

// ---------------- per-row SpMM helpers (CSR in shared memory) ----------------
__device__ __forceinline__ float row_bjac(const float* __restrict__ in, int r, int lr, int lane,
                                          const unsigned short* __restrict__ sc,
                                          const float* __restrict__ ssinv,
                                          const int* __restrict__ scnt) {
    int cnt = scnt[lr]; cnt = cnt > ROWCAP ? ROWCAP : cnt;
    const unsigned short* cp = sc + lr * ROWCAP;
    float acc = 0.f;
#pragma unroll 8
    for (int j = 0; j < cnt; ++j)
        acc += __ldcg(in + (int)cp[j] * FF + lane);
    return __ldcg(in + r * FF + lane) - ssinv[lr] * acc;
}

__device__ __forceinline__ float row_jac(const float* __restrict__ yk, const float* __restrict__ bj,
                                         int r, int lr, int lane,
                                         const unsigned short* __restrict__ sc,
                                         const float* __restrict__ swv,
                                         const int* __restrict__ scnt) {
    int cnt = scnt[lr]; cnt = cnt > ROWCAP ? ROWCAP : cnt;
    const unsigned short* cp = sc + lr * ROWCAP;
    const float* wp = swv + lr * ROWCAP;
    float acc = 0.f;
#pragma unroll 8
    for (int j = 0; j < cnt; ++j)
        acc += wp[j] * __ldcg(yk + (int)cp[j] * FF + lane);
    return acc + __ldcg(bj + r * FF + lane);
}

// ---------------- the one persistent kernel ----------------
__global__ void __launch_bounds__(TPB, 1)
cayley_all(const float* __restrict__ x, const int* __restrict__ ei,
           const float* __restrict__ ph, const float* __restrict__ palpha,
           const float* __restrict__ Wr0, const float* __restrict__ Wc0a,
           const float* __restrict__ Wc0b, const float* __restrict__ Wr1,
           const float* __restrict__ Wc1a, const float* __restrict__ Wc1b,
           const float* __restrict__ pw, const float* __restrict__ lw,
           const float* __restrict__ lb, float* __restrict__ out) {
    // scratch region reused per phase: setup deg+bitmap (19896B) / sW (12288B) / keys (24000B)
    __shared__ __align__(16) unsigned char s_raw[24000 + NWARP * FF * 4];
    __shared__ unsigned short s_col[NRMAX * ROWCAP];
    __shared__ float s_wv[NRMAX * ROWCAP];
    __shared__ int s_cnt[NRMAX];
    __shared__ float s_sinv[NRMAX];

    const int tid  = threadIdx.x;
    const int lane = tid & 31;
    const int wid  = tid >> 5;
    const int bid  = blockIdx.x;

    // balanced row partition: blocks 0..39 get 21 rows, 40..147 get 20
    const int r0    = (bid < 40) ? bid * 21 : 840 + (bid - 40) * 20;
    const int nrows = (bid < 40) ? 21 : 20;

    unsigned int bar = *(volatile unsigned int*)&g_flags[bid * 8];  // monotonic base

    const int* rowp = ei;
    const int* colp = ei + EE;
    const float hh = __ldg(ph);
    const float aa = __ldg(palpha);

    // pool_w norm (once)
    float pwv = __ldg(pw + lane);
    float nv = pwv * pwv;
#pragma unroll
    for (int o = 16; o > 0; o >>= 1) nv += __shfl_xor_sync(0xffffffffu, nv, o);
    const float pnorm = sqrtf(nv);

    // ---- setup: local CSR from full edge scan (no grid barriers) ----
    {
        int* s_deg = (int*)s_raw;                       // 3000 ints
        unsigned int* s_bm = (unsigned int*)(s_raw + 12000);  // BMW words
        for (int i = tid; i < NN; i += TPB) s_deg[i] = 0;
        for (int i = tid; i < BMW; i += TPB) s_bm[i] = 0;
        if (tid < NRMAX) s_cnt[tid] = 0;
        __syncthreads();

        const int4* r4 = (const int4*)rowp;
        const int4* c4 = (const int4*)colp;
        for (int q = tid; q < EE / 4; q += TPB) {
            int4 rr = __ldg(&r4[q]);
            int4 cc = __ldg(&c4[q]);
            int rs[4] = { rr.x, rr.y, rr.z, rr.w };
            int cs[4] = { cc.x, cc.y, cc.z, cc.w };
#pragma unroll
            for (int t = 0; t < 4; ++t) {
                int r = rs[t], c = cs[t];
                atomicAdd(&s_deg[r], 1);                // degree with multiplicity
                int lr = r - r0;
                if (lr >= 0 && lr < nrows) {
                    int bit = lr * NN + c;
                    unsigned int m = 1u << (bit & 31);
                    unsigned int old = atomicOr(&s_bm[bit >> 5], m);
                    if (!(old & m)) {                   // dedup (.set semantics)
                        int pos = atomicAdd(&s_cnt[lr], 1);
                        if (pos < ROWCAP) s_col[lr * ROWCAP + pos] = (unsigned short)c;
                    }
                }
            }
        }
        __syncthreads();

        for (int idx = tid; idx < NRMAX * ROWCAP; idx += TPB) {
            int lr = idx / ROWCAP, j = idx % ROWCAP;
            if (lr < nrows) {
                int cnt = s_cnt[lr]; cnt = cnt > ROWCAP ? ROWCAP : cnt;
                if (j < cnt) {
                    int c = (int)s_col[idx];
                    s_wv[idx] = 1.0f / (((float)s_deg[c] - aa) * hh);  // invD[col]
                }
            }
        }
        if (tid < nrows)
            s_sinv[tid] = 1.0f / ((float)s_deg[r0 + tid] - aa);
        __syncthreads();
    }

#define PHASE_BJAC(IN, OUT) do { \
        if (wid < nrows) { int r = r0 + wid; \
            OUT[r * FF + lane] = row_bjac(IN, r, wid, lane, s_col, s_sinv, s_cnt); } \
        gsync(++bar); } while (0)

#define PHASE_JAC(YK, BJ, OUT) do { \
        if (wid < nrows) { int r = r0 + wid; \
            OUT[r * FF + lane] = row_jac(YK, BJ, r, wid, lane, s_col, s_wv, s_cnt); } \
        gsync(++bar); } while (0)

    float myscore = 0.f, myxout = 0.f;

    // ================= layer 0 =================
    PHASE_BJAC(x, g_A);
    PHASE_JAC(g_A, g_A, g_B);
    PHASE_JAC(g_B, g_A, g_C);
    PHASE_JAC(g_C, g_A, g_B);
    PHASE_JAC(g_B, g_A, g_C);
    PHASE_JAC(g_C, g_A, g_Y1);      // order-0 result
    PHASE_BJAC(g_Y1, g_A);
    PHASE_JAC(g_A, g_A, g_B);
    PHASE_JAC(g_B, g_A, g_C);
    PHASE_JAC(g_C, g_A, g_B);
    PHASE_JAC(g_B, g_A, g_C);
    // fused: last jac (order-1) + outgemm -> X1
    {
        float* sW = (float*)s_raw;
        for (int t = tid; t < FF * FF; t += TPB) {
            int f = t >> 5, k = t & 31;
            sW[k * FF + f]        = __ldg(Wr0 + t);
            sW[1024 + k * FF + f] = __ldg(Wc0a + t);
            sW[2048 + k * FF + f] = __ldg(Wc0b + t);
        }
        __syncthreads();
        if (wid < nrows) {
            int r = r0 + wid;
            float y2 = row_jac(g_C, g_A, r, wid, lane, s_col, s_wv, s_cnt);
            float y1 = __ldcg(g_Y1 + r * FF + lane);
            float xo = __ldg(x + r * FF + lane);
            float acc = 0.f;
#pragma unroll
            for (int k = 0; k < FF; ++k) {
                float xv  = __shfl_sync(0xffffffffu, xo, k);
                float y1v = __shfl_sync(0xffffffffu, y1, k);
                float y2v = __shfl_sync(0xffffffffu, y2, k);
                acc += xv * sW[k * FF + lane]
                     + 2.f * y1v * sW[1024 + k * FF + lane]
                     + 2.f * y2v * sW[2048 + k * FF + lane];
            }
            g_X1[r * FF + lane] = fmaxf(acc, 0.f);
        }
        gsync(++bar);
    }

    // ================= layer 1 =================
    PHASE_BJAC(g_X1, g_A);
    PHASE_JAC(g_A, g_A, g_B);
    PHASE_JAC(g_B, g_A, g_C);
    PHASE_JAC(g_C, g_A, g_B);
    PHASE_JAC(g_B, g_A, g_C);
    PHASE_JAC(g_C, g_A, g_Y1);
    PHASE_BJAC(g_Y1, g_A);
    PHASE_JAC(g_A, g_A, g_B);
    PHASE_JAC(g_B, g_A, g_C);
    PHASE_JAC(g_C, g_A, g_B);
    PHASE_JAC(g_B, g_A, g_C);
    // fused: last jac + outgemm + score/keys (X2 stays in registers)
    {
        float* sW = (float*)s_raw;
        for (int t = tid; t < FF * FF; t += TPB) {
            int f = t >> 5, k = t & 31;
            sW[k * FF + f]        = __ldg(Wr1 + t);
            sW[1024 + k * FF + f] = __ldg(Wc1a + t);
            sW[2048 + k * FF + f] = __ldg(Wc1b + t);
        }
        __syncthreads();
        if (wid < nrows) {
            int r = r0 + wid;
            float y2 = row_jac(g_C, g_A, r, wid, lane, s_col, s_wv, s_cnt);
            float y1 = __ldcg(g_Y1 + r * FF + lane);
            float xo = __ldcg(g_X1 + r * FF + lane);
            float acc = 0.f;
#pragma unroll
            for (int k = 0; k < FF; ++k) {
                float xv  = __shfl_sync(0xffffffffu, xo, k);
                float y1v = __shfl_sync(0xffffffffu, y1, k);
                float y2v = __shfl_sync(0xffffffffu, y2, k);
                acc += xv * sW[k * FF + lane]
                     + 2.f * y1v * sW[1024 + k * FF + lane]
                     + 2.f * y2v * sW[2048 + k * FF + lane];
            }
            myxout = fmaxf(acc, 0.f);
            float v = myxout * pwv;
#pragma unroll
            for (int o = 16; o > 0; o >>= 1) v += __shfl_xor_sync(0xffffffffu, v, o);
            myscore = tanhf(v / pnorm);
            if (lane == 0)
                g_keys[r] = ((unsigned long long)f2ord(myscore) << 32)
                          | (unsigned long long)(0xFFFFFFFFu - (unsigned int)r);
        }
        gsync(++bar);   // barrier 24
    }

    // ---- rank + weighted partial sum ----
    {
        unsigned long long* sk = (unsigned long long*)s_raw;
        float* spart = (float*)(s_raw + 24000);
        for (int i = tid; i < NN; i += TPB) sk[i] = (unsigned long long)__ldcg((const unsigned long long*)(g_keys + i));
        __syncthreads();
        float contrib = 0.f;
        if (wid < nrows) {
            int r = r0 + wid;
            unsigned long long ki = ((unsigned long long)f2ord(myscore) << 32)
                                  | (unsigned long long)(0xFFFFFFFFu - (unsigned int)r);
            int c2 = 0;
            for (int j = lane; j < NN; j += 32) c2 += (sk[j] < ki) ? 1 : 0;
#pragma unroll
            for (int o = 16; o > 0; o >>= 1) c2 += __shfl_xor_sync(0xffffffffu, c2, o);
            float coef = (c2 < EXCL && myscore < 0.f) ? 0.f : myscore;
            contrib = coef * myxout;
        }
        spart[wid * FF + lane] = contrib;
        __syncthreads();
        if (wid == 0) {
            float t = 0.f;
#pragma unroll
            for (int q = 0; q < NWARP; ++q) t += spart[q * FF + lane];
            g_part[bid * FF + lane] = t;
        }
        gsync(++bar);   // barrier 25
    }

    // ---- block 0: final reduce + linear ----
    if (bid == 0) {
        float* spart = (float*)(s_raw + 24000);
        float a = 0.f;
        for (int b = wid; b < GRID; b += NWARP) a += __ldcg(g_part + b * FF + lane);
        spart[wid * FF + lane] = a;
        __syncthreads();
        if (wid == 0) {
            float t = 0.f;
#pragma unroll
            for (int q = 0; q < NWARP; ++q) t += spart[q * FF + lane];
            spart[lane] = t * (1.0f / KSELF);
            __syncwarp();
            if (lane < 8) {
                float o = __ldg(lb + lane);
#pragma unroll
                for (int f = 0; f < FF; ++f) o += spart[f] * __ldg(lw + lane * FF + f);
                out[lane] = o;
            }
        }
    }
}

// ---------------- host side ----------------
extern "C" void kernel_launch(void* const* d_in, const int* in_sizes, int n_in,
                              void* d_out, int out_size) {
    const float* x     = (const float*)d_in[0];
    const int*   ei    = (const int*)d_in[1];
    const float* h     = (const float*)d_in[2];
    const float* alpha = (const float*)d_in[3];
    const float* Wr0   = (const float*)d_in[4];
    const float* Wc0a  = (const float*)d_in[5];
    const float* Wc0b  = (const float*)d_in[6];
    const float* Wr1   = (const float*)d_in[7];
    const float* Wc1a  = (const float*)d_in[8];
    const float* Wc1b  = (const float*)d_in[9];
    const float* pw    = (const float*)d_in[10];
    const float* lw    = (const float*)d_in[11];
    const float* lb    = (const float*)d_in[12];

    cayley_all<<<GRID, TPB>>>(x, ei, h, alpha, Wr0, Wc0a, Wc0b,
                              Wr1, Wc1a, Wc1b, pw, lw, lb, (float*)d_out);
}

// round 4
// speedup vs baseline: 1.0221x; 1.0221x over previous
#include <cuda_runtime.h>
#include <math.h>

#define NN 3000
#define EE 48000
#define FF 32
#define GRID 148
#define TPB 672            // 21 warps
#define NWARP 21
#define EXCL 1200
#define KSELF 10800.0f
#define ROWCAP 64
#define NRMAX 21

// ---------------- static global state ----------------
__device__ unsigned int g_gen[(size_t)NN * NN];   // 36 MB generation-dedup array (never zeroed)
__device__ int g_deg[NN];                          // zeroed at end of each run
__device__ int g_rcnt[NN];                         // zeroed at end of each run
__device__ unsigned short g_cols[NN * ROWCAP];
__device__ float g_A[NN * FF];
__device__ float g_B[NN * FF];
__device__ float g_C[NN * FF];
__device__ float g_Y1[NN * FF];
__device__ float g_X1[NN * FF];
__device__ unsigned long long g_keys[NN];
__device__ float g_part[GRID * FF];
__device__ unsigned int g_flags[GRID * 8];         // 32B-strided, monotonic

// ---------------- scoped release/acquire barrier (no MEMBAR.GL / IVALL) ----------------
__device__ __forceinline__ void st_release_gpu(unsigned int* p, unsigned int v) {
    asm volatile("st.release.gpu.u32 [%0], %1;" :: "l"(p), "r"(v) : "memory");
}
__device__ __forceinline__ unsigned int ld_acquire_gpu(unsigned int* p) {
    unsigned int v;
    asm volatile("ld.acquire.gpu.u32 %0, [%1];" : "=r"(v) : "l"(p) : "memory");
    return v;
}

__device__ __forceinline__ void gsync(unsigned int target) {
    __syncthreads();
    if (threadIdx.x == 0)
        st_release_gpu(&g_flags[blockIdx.x * 8], target);
    if (threadIdx.x < 32) {
        bool ok;
        do {
            ok = true;
#pragma unroll
            for (int k = 0; k < 5; ++k) {
                int b = (int)threadIdx.x + k * 32;
                if (b < GRID)
                    ok &= (ld_acquire_gpu(&g_flags[b * 8]) >= target);
            }
        } while (!ok);
    }
    __syncthreads();
}

__device__ __forceinline__ unsigned int f2ord(float f) {
    unsigned int u = __float_as_uint(f);
    return (u & 0x80000000u) ? ~u : (u | 0x80000000u);
}

// ---------------- per-row SpMM helpers (CSR in shared memory) ----------------
__device__ __forceinline__ float row_bjac(const float* __restrict__ in, int r, int lr, int lane,
                                          const unsigned short* __restrict__ sc,
                                          const float* __restrict__ ssinv,
                                          const int* __restrict__ scnt) {
    float diag = __ldcg(in + r * FF + lane);
    int cnt = scnt[lr];
    const unsigned short* cp = sc + lr * ROWCAP;
    float acc = 0.f;
#pragma unroll 8
    for (int j = 0; j < cnt; ++j)
        acc += __ldcg(in + (int)cp[j] * FF + lane);
    return diag - ssinv[lr] * acc;
}

__device__ __forceinline__ float row_jac(const float* __restrict__ yk, const float* __restrict__ bj,
                                         int r, int lr, int lane,
                                         const unsigned short* __restrict__ sc,
                                         const float* __restrict__ swv,
                                         const int* __restrict__ scnt) {
    float bjv = __ldcg(bj + r * FF + lane);
    int cnt = scnt[lr];
    const unsigned short* cp = sc + lr * ROWCAP;
    const float* wp = swv + lr * ROWCAP;
    float acc = 0.f;
#pragma unroll 8
    for (int j = 0; j < cnt; ++j)
        acc += wp[j] * __ldcg(yk + (int)cp[j] * FF + lane);
    return acc + bjv;
}

// ---------------- the one persistent kernel ----------------
__global__ void __launch_bounds__(TPB, 1)
cayley_all(const float* __restrict__ x, const int* __restrict__ ei,
           const float* __restrict__ ph, const float* __restrict__ palpha,
           const float* __restrict__ Wr0, const float* __restrict__ Wc0a,
           const float* __restrict__ Wc0b, const float* __restrict__ Wr1,
           const float* __restrict__ Wc1a, const float* __restrict__ Wc1b,
           const float* __restrict__ pw, const float* __restrict__ lw,
           const float* __restrict__ lb, float* __restrict__ out) {
    __shared__ __align__(16) unsigned char s_raw[24000 + NWARP * FF * 4];  // keys / sW / partials
    __shared__ unsigned short s_col[NRMAX * ROWCAP];
    __shared__ float s_wv[NRMAX * ROWCAP];
    __shared__ int s_cnt[NRMAX];
    __shared__ float s_sinv[NRMAX];

    const int tid  = threadIdx.x;
    const int lane = tid & 31;
    const int wid  = tid >> 5;
    const int bid  = blockIdx.x;

    // balanced rows: blocks 0..39 get 21, 40..147 get 20
    const int r0    = (bid < 40) ? bid * 21 : 840 + (bid - 40) * 20;
    const int nrows = (bid < 40) ? 21 : 20;

    unsigned int bar = g_flags[bid * 8];        // monotonic base (all equal at entry)
    const unsigned int gen = bar + 1u;          // unique per run, same for all blocks

    const int* rowp = ei;
    const int* colp = ei + EE;
    const float hh = __ldg(ph);
    const float aa = __ldg(palpha);

    // pool_w norm
    float pwv = __ldg(pw + lane);
    float nv = pwv * pwv;
#pragma unroll
    for (int o = 16; o > 0; o >>= 1) nv += __shfl_xor_sync(0xffffffffu, nv, o);
    const float pnorm = sqrtf(nv);

    // ---- S1: distributed edge build (1 edge / thread) ----
    {
        int e = bid * TPB + tid;
        if (e < EE) {
            int r = __ldg(rowp + e), c = __ldg(colp + e);
            atomicAdd(&g_deg[r], 1);                              // degree with multiplicity
            unsigned int old = atomicMax(&g_gen[(size_t)r * NN + c], gen);
            if (old < gen) {                                      // first occurrence this run
                int pos = atomicAdd(&g_rcnt[r], 1);
                if (pos < ROWCAP) g_cols[r * ROWCAP + pos] = (unsigned short)c;
            }
        }
    }
    gsync(++bar);   // B1

    // ---- bjac0 (layer0 order0), fused with CSR->smem + wv/sinv ----
    {
        if (tid < nrows) {
            int r = r0 + tid;
            int c2 = g_rcnt[r];
            s_cnt[tid] = c2 > ROWCAP ? ROWCAP : c2;
            s_sinv[tid] = 1.0f / ((float)g_deg[r] - aa);
        }
        __syncthreads();
        for (int idx = tid; idx < NRMAX * ROWCAP; idx += TPB) {
            int lr = idx >> 6, j = idx & 63;
            if (lr < nrows && j < s_cnt[lr]) {
                int c = (int)g_cols[(r0 + lr) * ROWCAP + j];
                s_col[idx] = (unsigned short)c;
                s_wv[idx] = 1.0f / (((float)g_deg[c] - aa) * hh);  // invD[col]
            }
        }
        __syncthreads();
        if (wid < nrows) {
            int r = r0 + wid;
            g_A[r * FF + lane] = row_bjac(x, r, wid, lane, s_col, s_sinv, s_cnt);
        }
    }
    gsync(++bar);   // B2

#define PHASE_BJAC(IN, OUT) do { \
        if (wid < nrows) { int r = r0 + wid; \
            OUT[r * FF + lane] = row_bjac(IN, r, wid, lane, s_col, s_sinv, s_cnt); } \
        gsync(++bar); } while (0)

#define PHASE_JAC(YK, BJ, OUT) do { \
        if (wid < nrows) { int r = r0 + wid; \
            OUT[r * FF + lane] = row_jac(YK, BJ, r, wid, lane, s_col, s_wv, s_cnt); } \
        gsync(++bar); } while (0)

    float myscore = 0.f, myxout = 0.f;

    // ---- layer 0 order 0 remaining jacs ----
    PHASE_JAC(g_A, g_A, g_B);      // B3
    PHASE_JAC(g_B, g_A, g_C);      // B4
    PHASE_JAC(g_C, g_A, g_B);      // B5
    PHASE_JAC(g_B, g_A, g_C);      // B6
    PHASE_JAC(g_C, g_A, g_Y1);     // B7  order-0 result

    // ---- layer 0 order 1 ----
    PHASE_BJAC(g_Y1, g_A);         // B8
    PHASE_JAC(g_A, g_A, g_B);      // B9
    PHASE_JAC(g_B, g_A, g_C);      // B10
    PHASE_JAC(g_C, g_A, g_B);      // B11
    PHASE_JAC(g_B, g_A, g_C);      // B12
    // fused last jac + outgemm -> X1
    {
        float* sW = (float*)s_raw;
        for (int t = tid; t < FF * FF; t += TPB) {
            int f = t >> 5, k = t & 31;
            sW[k * FF + f]        = __ldg(Wr0 + t);
            sW[1024 + k * FF + f] = __ldg(Wc0a + t);
            sW[2048 + k * FF + f] = __ldg(Wc0b + t);
        }
        __syncthreads();
        if (wid < nrows) {
            int r = r0 + wid;
            float y2 = row_jac(g_C, g_A, r, wid, lane, s_col, s_wv, s_cnt);
            float y1 = __ldcg(g_Y1 + r * FF + lane);
            float xo = __ldg(x + r * FF + lane);
            float acc = 0.f;
#pragma unroll
            for (int k = 0; k < FF; ++k) {
                float xv  = __shfl_sync(0xffffffffu, xo, k);
                float y1v = __shfl_sync(0xffffffffu, y1, k);
                float y2v = __shfl_sync(0xffffffffu, y2, k);
                acc += xv * sW[k * FF + lane]
                     + 2.f * y1v * sW[1024 + k * FF + lane]
                     + 2.f * y2v * sW[2048 + k * FF + lane];
            }
            g_X1[r * FF + lane] = fmaxf(acc, 0.f);
        }
        gsync(++bar);   // B13
    }

    // ---- layer 1 order 0 ----
    PHASE_BJAC(g_X1, g_A);         // B14
    PHASE_JAC(g_A, g_A, g_B);      // B15
    PHASE_JAC(g_B, g_A, g_C);      // B16
    PHASE_JAC(g_C, g_A, g_B);      // B17
    PHASE_JAC(g_B, g_A, g_C);      // B18
    PHASE_JAC(g_C, g_A, g_Y1);     // B19

    // ---- layer 1 order 1 ----
    PHASE_BJAC(g_Y1, g_A);         // B20
    PHASE_JAC(g_A, g_A, g_B);      // B21
    PHASE_JAC(g_B, g_A, g_C);      // B22
    PHASE_JAC(g_C, g_A, g_B);      // B23
    PHASE_JAC(g_B, g_A, g_C);      // B24
    // fused last jac + outgemm + score/keys (X2 stays in registers)
    {
        float* sW = (float*)s_raw;
        for (int t = tid; t < FF * FF; t += TPB) {
            int f = t >> 5, k = t & 31;
            sW[k * FF + f]        = __ldg(Wr1 + t);
            sW[1024 + k * FF + f] = __ldg(Wc1a + t);
            sW[2048 + k * FF + f] = __ldg(Wc1b + t);
        }
        __syncthreads();
        if (wid < nrows) {
            int r = r0 + wid;
            float y2 = row_jac(g_C, g_A, r, wid, lane, s_col, s_wv, s_cnt);
            float y1 = __ldcg(g_Y1 + r * FF + lane);
            float xo = __ldcg(g_X1 + r * FF + lane);
            float acc = 0.f;
#pragma unroll
            for (int k = 0; k < FF; ++k) {
                float xv  = __shfl_sync(0xffffffffu, xo, k);
                float y1v = __shfl_sync(0xffffffffu, y1, k);
                float y2v = __shfl_sync(0xffffffffu, y2, k);
                acc += xv * sW[k * FF + lane]
                     + 2.f * y1v * sW[1024 + k * FF + lane]
                     + 2.f * y2v * sW[2048 + k * FF + lane];
            }
            myxout = fmaxf(acc, 0.f);
            float v = myxout * pwv;
#pragma unroll
            for (int o = 16; o > 0; o >>= 1) v += __shfl_xor_sync(0xffffffffu, v, o);
            myscore = tanhf(v / pnorm);
            if (lane == 0)
                g_keys[r] = ((unsigned long long)f2ord(myscore) << 32)
                          | (unsigned long long)(0xFFFFFFFFu - (unsigned int)r);
        }
        gsync(++bar);   // B25
    }

    // ---- rank + weighted partial sums + counter re-zero for next run ----
    {
        unsigned long long* sk = (unsigned long long*)s_raw;
        float* spart = (float*)(s_raw + 24000);
        for (int i = tid; i < NN; i += TPB)
            sk[i] = __ldcg((const unsigned long long*)(g_keys + i));
        // re-zero per-run counters (last read was in bjac0 phase)
        if (tid < nrows) { g_deg[r0 + tid] = 0; g_rcnt[r0 + tid] = 0; }
        __syncthreads();
        float contrib = 0.f;
        if (wid < nrows) {
            int r = r0 + wid;
            unsigned long long ki = ((unsigned long long)f2ord(myscore) << 32)
                                  | (unsigned long long)(0xFFFFFFFFu - (unsigned int)r);
            int c2 = 0;
            for (int j = lane; j < NN; j += 32) c2 += (sk[j] < ki) ? 1 : 0;
#pragma unroll
            for (int o = 16; o > 0; o >>= 1) c2 += __shfl_xor_sync(0xffffffffu, c2, o);
            float coef = (c2 < EXCL && myscore < 0.f) ? 0.f : myscore;
            contrib = coef * myxout;
        }
        spart[wid * FF + lane] = contrib;
        __syncthreads();
        if (wid == 0) {
            float t = 0.f;
#pragma unroll
            for (int q = 0; q < NWARP; ++q) t += spart[q * FF + lane];
            g_part[bid * FF + lane] = t;
        }
        gsync(++bar);   // B26
    }

    // ---- block 0: final reduce + linear ----
    if (bid == 0) {
        float* spart = (float*)(s_raw + 24000);
        float a = 0.f;
        for (int b = wid; b < GRID; b += NWARP) a += __ldcg(g_part + b * FF + lane);
        spart[wid * FF + lane] = a;
        __syncthreads();
        if (wid == 0) {
            float t = 0.f;
#pragma unroll
            for (int q = 0; q < NWARP; ++q) t += spart[q * FF + lane];
            spart[lane] = t * (1.0f / KSELF);
            __syncwarp();
            if (lane < 8) {
                float o = __ldg(lb + lane);
#pragma unroll
                for (int f = 0; f < FF; ++f) o += spart[f] * __ldg(lw + lane * FF + f);
                out[lane] = o;
            }
        }
    }
}

// ---------------- host side ----------------
extern "C" void kernel_launch(void* const* d_in, const int* in_sizes, int n_in,
                              void* d_out, int out_size) {
    const float* x     = (const float*)d_in[0];
    const int*   ei    = (const int*)d_in[1];
    const float* h     = (const float*)d_in[2];
    const float* alpha = (const float*)d_in[3];
    const float* Wr0   = (const float*)d_in[4];
    const float* Wc0a  = (const float*)d_in[5];
    const float* Wc0b  = (const float*)d_in[6];
    const float* Wr1   = (const float*)d_in[7];
    const float* Wc1a  = (const float*)d_in[8];
    const float* Wc1b  = (const float*)d_in[9];
    const float* pw    = (const float*)d_in[10];
    const float* lw    = (const float*)d_in[11];
    const float* lb    = (const float*)d_in[12];

    cayley_all<<<GRID, TPB>>>(x, ei, h, alpha, Wr0, Wc0a, Wc0b,
                              Wr1, Wc1a, Wc1b, pw, lw, lb, (float*)d_out);
}

// round 5
// speedup vs baseline: 1.6171x; 1.5822x over previous
#include <cuda_runtime.h>
#include <math.h>

#define NN 3000
#define EE 48000
#define FF 32
#define GRID 148
#define TPB 672            // 21 warps
#define NWARP 21
#define EXCL 1200
#define KSELF 10800.0f
#define ROWCAP 64
#define NRMAX 21

// ---------------- static global state ----------------
__device__ unsigned int g_gen[(size_t)NN * NN];   // 36 MB generation-dedup array (never zeroed)
__device__ unsigned int g_run;                     // run epoch (written at end of each run)
__device__ int g_deg[NN];                          // zeroed at end of each run
__device__ int g_rcnt[NN];                         // zeroed at end of each run
__device__ unsigned short g_cols[NN * ROWCAP];
__device__ float g_A[NN * FF];
__device__ float g_B[NN * FF];
__device__ float g_C[NN * FF];
__device__ float g_Y1[NN * FF];
__device__ float g_X1[NN * FF];
__device__ unsigned long long g_keys[NN];
__device__ float g_part[GRID * FF];
__device__ unsigned int g_ctr;                     // barrier ticket counter (monotonic)

// ---------------- ticket barrier: one atomic arrive + one-line acquire poll ----------------
__device__ __forceinline__ void gsync() {
    __syncthreads();
    if (threadIdx.x == 0) {
        unsigned int old;
        asm volatile("atom.release.gpu.add.u32 %0, [%1], 1;"
                     : "=r"(old) : "l"(&g_ctr) : "memory");
        unsigned int target = old - (old % GRID) + GRID;   // next multiple of GRID
        unsigned int v;
        do {
            asm volatile("ld.acquire.gpu.u32 %0, [%1];" : "=r"(v) : "l"(&g_ctr) : "memory");
        } while ((int)(v - target) < 0);
    }
    __syncthreads();
}

__device__ __forceinline__ unsigned int f2ord(float f) {
    unsigned int u = __float_as_uint(f);
    return (u & 0x80000000u) ? ~u : (u | 0x80000000u);
}

// ---------------- the one persistent kernel ----------------
__global__ void __launch_bounds__(TPB, 1)
cayley_all(const float* __restrict__ x, const int* __restrict__ ei,
           const float* __restrict__ ph, const float* __restrict__ palpha,
           const float* __restrict__ Wr0, const float* __restrict__ Wc0a,
           const float* __restrict__ Wc0b, const float* __restrict__ Wr1,
           const float* __restrict__ Wc1a, const float* __restrict__ Wc1b,
           const float* __restrict__ pw, const float* __restrict__ lw,
           const float* __restrict__ lb, float* __restrict__ out) {
    __shared__ __align__(16) unsigned char s_raw[24000 + NWARP * FF * 4];  // keys / sW / partials
    __shared__ __align__(8) float2 s_ew[NRMAX * ROWCAP];   // (byte-offset bits, weight) per edge
    __shared__ int s_cnt[NRMAX];
    __shared__ float s_sinv[NRMAX];

    const int tid  = threadIdx.x;
    const int lane = tid & 31;
    const int wid  = tid >> 5;
    const int bid  = blockIdx.x;

    // balanced rows: blocks 0..39 get 21, 40..147 get 20
    const int r0    = (bid < 40) ? bid * 21 : 840 + (bid - 40) * 20;
    const int nrows = (bid < 40) ? 21 : 20;

    const unsigned int gen = g_run + 1u;     // unique per run (runs serialize)

    const int* rowp = ei;
    const int* colp = ei + EE;
    const float hh = __ldg(ph);
    const float aa = __ldg(palpha);

    // pool_w norm
    float pwv = __ldg(pw + lane);
    float nv = pwv * pwv;
#pragma unroll
    for (int o = 16; o > 0; o >>= 1) nv += __shfl_xor_sync(0xffffffffu, nv, o);
    const float pnorm = sqrtf(nv);

    // ---- S1: distributed edge build (1 edge / thread) ----
    {
        int e = bid * TPB + tid;
        if (e < EE) {
            int r = __ldg(rowp + e), c = __ldg(colp + e);
            atomicAdd(&g_deg[r], 1);                              // degree with multiplicity
            unsigned int old = atomicMax(&g_gen[(size_t)r * NN + c], gen);
            if (old < gen) {                                      // first occurrence this run
                int pos = atomicAdd(&g_rcnt[r], 1);
                if (pos < ROWCAP) g_cols[r * ROWCAP + pos] = (unsigned short)c;
            }
        }
    }
    gsync();   // B1

    // ---- bjac0 (layer0 order0), fused with CSR->smem + wv/sinv ----
    {
        if (tid < nrows) {
            int r = r0 + tid;
            int c2 = g_rcnt[r];
            s_cnt[tid] = c2 > ROWCAP ? ROWCAP : c2;
            s_sinv[tid] = 1.0f / ((float)g_deg[r] - aa);
        }
        __syncthreads();
        for (int idx = tid; idx < NRMAX * ROWCAP; idx += TPB) {
            int lr = idx >> 6, j = idx & 63;
            if (lr < nrows && j < s_cnt[lr]) {
                int c = (int)g_cols[(r0 + lr) * ROWCAP + j];
                float w = 1.0f / (((float)g_deg[c] - aa) * hh);   // invD[col]
                s_ew[idx] = make_float2(__int_as_float(c * (FF * 4)), w);
            }
        }
        __syncthreads();
    }

    // per-row gather helpers (lambda-style macros using s_ew/s_cnt/s_sinv)
#define ROW_BJAC(IN, RES) do { \
        int r = r0 + wid; \
        float diag = __ldcg((IN) + r * FF + lane); \
        int cnt = s_cnt[wid]; \
        const float2* ep = s_ew + wid * ROWCAP; \
        float acc = 0.f; \
        _Pragma("unroll 8") \
        for (int j = 0; j < cnt; ++j) { \
            float2 e = ep[j]; \
            acc += __ldcg((const float*)((const char*)(IN) + __float_as_int(e.x)) + lane); \
        } \
        RES = diag - s_sinv[wid] * acc; \
    } while (0)

#define ROW_JAC(YK, BJ, RES) do { \
        int r = r0 + wid; \
        float bjv = __ldcg((BJ) + r * FF + lane); \
        int cnt = s_cnt[wid]; \
        const float2* ep = s_ew + wid * ROWCAP; \
        float acc = 0.f; \
        _Pragma("unroll 8") \
        for (int j = 0; j < cnt; ++j) { \
            float2 e = ep[j]; \
            acc += e.y * __ldcg((const float*)((const char*)(YK) + __float_as_int(e.x)) + lane); \
        } \
        RES = acc + bjv; \
    } while (0)

#define PHASE_BJAC(IN, OUT) do { \
        if (wid < nrows) { float rres; ROW_BJAC(IN, rres); \
            OUT[(r0 + wid) * FF + lane] = rres; } \
        gsync(); } while (0)

#define PHASE_JAC(YK, BJ, OUT) do { \
        if (wid < nrows) { float rres; ROW_JAC(YK, BJ, rres); \
            OUT[(r0 + wid) * FF + lane] = rres; } \
        gsync(); } while (0)

    float myscore = 0.f, myxout = 0.f;

    // ---- layer 0 order 0 ----
    PHASE_BJAC(x, g_A);            // B2
    PHASE_JAC(g_A, g_A, g_B);      // B3
    PHASE_JAC(g_B, g_A, g_C);      // B4
    PHASE_JAC(g_C, g_A, g_B);      // B5
    PHASE_JAC(g_B, g_A, g_C);      // B6
    PHASE_JAC(g_C, g_A, g_Y1);     // B7  order-0 result

    // ---- layer 0 order 1 ----
    PHASE_BJAC(g_Y1, g_A);         // B8
    PHASE_JAC(g_A, g_A, g_B);      // B9
    PHASE_JAC(g_B, g_A, g_C);      // B10
    PHASE_JAC(g_C, g_A, g_B);      // B11
    PHASE_JAC(g_B, g_A, g_C);      // B12
    // fused last jac + outgemm -> X1
    {
        float* sW = (float*)s_raw;
        for (int t = tid; t < FF * FF; t += TPB) {
            int f = t >> 5, k = t & 31;
            sW[k * FF + f]        = __ldg(Wr0 + t);
            sW[1024 + k * FF + f] = __ldg(Wc0a + t);
            sW[2048 + k * FF + f] = __ldg(Wc0b + t);
        }
        __syncthreads();
        if (wid < nrows) {
            int r = r0 + wid;
            float y2; ROW_JAC(g_C, g_A, y2);
            float y1 = __ldcg(g_Y1 + r * FF + lane);
            float xo = __ldg(x + r * FF + lane);
            float acc = 0.f;
#pragma unroll
            for (int k = 0; k < FF; ++k) {
                float xv  = __shfl_sync(0xffffffffu, xo, k);
                float y1v = __shfl_sync(0xffffffffu, y1, k);
                float y2v = __shfl_sync(0xffffffffu, y2, k);
                acc += xv * sW[k * FF + lane]
                     + 2.f * y1v * sW[1024 + k * FF + lane]
                     + 2.f * y2v * sW[2048 + k * FF + lane];
            }
            g_X1[r * FF + lane] = fmaxf(acc, 0.f);
        }
        gsync();   // B13
    }

    // ---- layer 1 order 0 ----
    PHASE_BJAC(g_X1, g_A);         // B14
    PHASE_JAC(g_A, g_A, g_B);      // B15
    PHASE_JAC(g_B, g_A, g_C);      // B16
    PHASE_JAC(g_C, g_A, g_B);      // B17
    PHASE_JAC(g_B, g_A, g_C);      // B18
    PHASE_JAC(g_C, g_A, g_Y1);     // B19

    // ---- layer 1 order 1 ----
    PHASE_BJAC(g_Y1, g_A);         // B20
    PHASE_JAC(g_A, g_A, g_B);      // B21
    PHASE_JAC(g_B, g_A, g_C);      // B22
    PHASE_JAC(g_C, g_A, g_B);      // B23
    PHASE_JAC(g_B, g_A, g_C);      // B24
    // fused last jac + outgemm + score/keys (X2 stays in registers)
    {
        float* sW = (float*)s_raw;
        for (int t = tid; t < FF * FF; t += TPB) {
            int f = t >> 5, k = t & 31;
            sW[k * FF + f]        = __ldg(Wr1 + t);
            sW[1024 + k * FF + f] = __ldg(Wc1a + t);
            sW[2048 + k * FF + f] = __ldg(Wc1b + t);
        }
        __syncthreads();
        if (wid < nrows) {
            int r = r0 + wid;
            float y2; ROW_JAC(g_C, g_A, y2);
            float y1 = __ldcg(g_Y1 + r * FF + lane);
            float xo = __ldcg(g_X1 + r * FF + lane);
            float acc = 0.f;
#pragma unroll
            for (int k = 0; k < FF; ++k) {
                float xv  = __shfl_sync(0xffffffffu, xo, k);
                float y1v = __shfl_sync(0xffffffffu, y1, k);
                float y2v = __shfl_sync(0xffffffffu, y2, k);
                acc += xv * sW[k * FF + lane]
                     + 2.f * y1v * sW[1024 + k * FF + lane]
                     + 2.f * y2v * sW[2048 + k * FF + lane];
            }
            myxout = fmaxf(acc, 0.f);
            float v = myxout * pwv;
#pragma unroll
            for (int o = 16; o > 0; o >>= 1) v += __shfl_xor_sync(0xffffffffu, v, o);
            myscore = tanhf(v / pnorm);
            if (lane == 0)
                g_keys[r] = ((unsigned long long)f2ord(myscore) << 32)
                          | (unsigned long long)(0xFFFFFFFFu - (unsigned int)r);
        }
        gsync();   // B25
    }

    // ---- rank + weighted partial sums + counter re-zero for next run ----
    {
        unsigned long long* sk = (unsigned long long*)s_raw;
        float* spart = (float*)(s_raw + 24000);
        for (int i = tid; i < NN; i += TPB)
            sk[i] = __ldcg((const unsigned long long*)(g_keys + i));
        if (tid < nrows) { g_deg[r0 + tid] = 0; g_rcnt[r0 + tid] = 0; }
        __syncthreads();
        float contrib = 0.f;
        if (wid < nrows) {
            int r = r0 + wid;
            unsigned long long ki = ((unsigned long long)f2ord(myscore) << 32)
                                  | (unsigned long long)(0xFFFFFFFFu - (unsigned int)r);
            int c2 = 0;
            for (int j = lane; j < NN; j += 32) c2 += (sk[j] < ki) ? 1 : 0;
#pragma unroll
            for (int o = 16; o > 0; o >>= 1) c2 += __shfl_xor_sync(0xffffffffu, c2, o);
            float coef = (c2 < EXCL && myscore < 0.f) ? 0.f : myscore;
            contrib = coef * myxout;
        }
        spart[wid * FF + lane] = contrib;
        __syncthreads();
        if (wid == 0) {
            float t = 0.f;
#pragma unroll
            for (int q = 0; q < NWARP; ++q) t += spart[q * FF + lane];
            g_part[bid * FF + lane] = t;
        }
        gsync();   // B26
    }

    // ---- block 0: final reduce + linear + run-epoch bump ----
    if (bid == 0) {
        float* spart = (float*)(s_raw + 24000);
        float a = 0.f;
        for (int b = wid; b < GRID; b += NWARP) a += __ldcg(g_part + b * FF + lane);
        spart[wid * FF + lane] = a;
        __syncthreads();
        if (wid == 0) {
            float t = 0.f;
#pragma unroll
            for (int q = 0; q < NWARP; ++q) t += spart[q * FF + lane];
            spart[lane] = t * (1.0f / KSELF);
            __syncwarp();
            if (lane < 8) {
                float o = __ldg(lb + lane);
#pragma unroll
                for (int f = 0; f < FF; ++f) o += spart[f] * __ldg(lw + lane * FF + f);
                out[lane] = o;
            }
            if (lane == 0) g_run = gen;   // epoch for next run (runs serialize)
        }
    }
}

// ---------------- host side ----------------
extern "C" void kernel_launch(void* const* d_in, const int* in_sizes, int n_in,
                              void* d_out, int out_size) {
    const float* x     = (const float*)d_in[0];
    const int*   ei    = (const int*)d_in[1];
    const float* h     = (const float*)d_in[2];
    const float* alpha = (const float*)d_in[3];
    const float* Wr0   = (const float*)d_in[4];
    const float* Wc0a  = (const float*)d_in[5];
    const float* Wc0b  = (const float*)d_in[6];
    const float* Wr1   = (const float*)d_in[7];
    const float* Wc1a  = (const float*)d_in[8];
    const float* Wc1b  = (const float*)d_in[9];
    const float* pw    = (const float*)d_in[10];
    const float* lw    = (const float*)d_in[11];
    const float* lb    = (const float*)d_in[12];

    cayley_all<<<GRID, TPB>>>(x, ei, h, alpha, Wr0, Wc0a, Wc0b,
                              Wr1, Wc1a, Wc1b, pw, lw, lb, (float*)d_out);
}